// round 7
// baseline (speedup 1.0000x reference)
#include <cuda_runtime.h>
#include <cuda_fp16.h>
#include <cstdint>

#define NJ 14
#define NB 2
#define NT 32768
#define NH 128
#define CIN 131

#define RS 68                 // row stride in u32 (272 B): 16B-aligned, ldmatrix conflict-free
// smem word offsets
#define CB_W   0              // CB[128][RS]  c tile (read-only, layer-0 A)
#define AH_W   8704           // AH[128][RS]  activations (layers 1-2, in-place)
#define WB_W   17408          // W[128][RS]
#define AH_BYTES 34816
#define WB_BYTES 69632
#define BIAS_W 26112          // [2][3][128]
#define W0P_W  26880          // [2][3][128]
#define W3_W   27648          // [2][128]
#define SCR_W  27904          // [128]
#define SMEM_BYTES 112640

__device__ uint32_t g_w16[NJ * 3 * 8192];          // fp16x2 weights [j][l][h(128)][kw(64)]
__device__ uint32_t g_c16[NB * 256 * 128 * 64];    // fp16x2 c tiles [b][tile][t(128)][kw(64)]

// ---------- helpers ----------
__device__ __forceinline__ uint32_t smem_u32(const void* p) {
    uint32_t a;
    asm("{ .reg .u64 t; cvta.to.shared.u64 t, %1; cvt.u32.u64 %0, t; }" : "=r"(a) : "l"(p));
    return a;
}
__device__ __forceinline__ void ldsm4(uint32_t* r, uint32_t addr) {
    asm volatile("ldmatrix.sync.aligned.m8n8.x4.shared.b16 {%0,%1,%2,%3}, [%4];"
                 : "=r"(r[0]), "=r"(r[1]), "=r"(r[2]), "=r"(r[3]) : "r"(addr));
}
__device__ __forceinline__ void mma16816(float* d, const uint32_t* a,
                                         uint32_t b0, uint32_t b1) {
    asm volatile(
        "mma.sync.aligned.m16n8k16.row.col.f32.f16.f16.f32 "
        "{%0,%1,%2,%3}, {%4,%5,%6,%7}, {%8,%9}, {%0,%1,%2,%3};"
        : "+f"(d[0]), "+f"(d[1]), "+f"(d[2]), "+f"(d[3])
        : "r"(a[0]), "r"(a[1]), "r"(a[2]), "r"(a[3]), "r"(b0), "r"(b1));
}
__device__ __forceinline__ void cpasync16(uint32_t dst, const void* src) {
    asm volatile("cp.async.ca.shared.global [%0], [%1], 16;" :: "r"(dst), "l"(src));
}
#define CP_COMMIT() asm volatile("cp.async.commit_group;" ::: "memory")
#define CP_WAIT0()  asm volatile("cp.async.wait_group 0;" ::: "memory")

__device__ __forceinline__ uint32_t h2bits(half2 h) {
    return *reinterpret_cast<uint32_t*>(&h);
}

// ---------- fused pre-conversion: weights (blocks 0..41) + c (blocks 42..553) ----------
__global__ void convert_all(const float* __restrict__ W0,
                            const float* __restrict__ W1,
                            const float* __restrict__ W2,
                            const float* __restrict__ c) {
    __shared__ uint32_t s[128 * 65];
    int bid = blockIdx.x;
    if (bid < 42) {
        int j = bid / 3, l = bid % 3;
        const float* W = (l == 0) ? W0 : ((l == 1) ? W1 : W2);
        int K = (l == 0) ? CIN : NH;
        int koff = (l == 0) ? 3 : 0;
        uint32_t* dst = g_w16 + (size_t)(j * 3 + l) * 8192;
        for (int i = threadIdx.x; i < 8192; i += blockDim.x) {
            int h = i >> 6, kw = i & 63;
            const float* row = W + ((size_t)j * NH + h) * K + koff;
            dst[i] = h2bits(__floats2half2_rn(row[2 * kw], row[2 * kw + 1]));
        }
    } else {
        int cid = bid - 42;
        int tile = cid & 255, b = cid >> 8;
        const float* cb = c + (size_t)b * NH * NT + tile * 128;
        uint32_t* dst = g_c16 + ((size_t)b * 256 + tile) * 8192;
        for (int i = threadIdx.x; i < 8192; i += 256) {
            int t = i & 127, kw = i >> 7;
            float v0 = __ldg(cb + (size_t)(2 * kw) * NT + t);
            float v1 = __ldg(cb + (size_t)(2 * kw + 1) * NT + t);
            s[t * 65 + kw] = h2bits(__floats2half2_rn(v0, v1));
        }
        __syncthreads();
        for (int i = threadIdx.x; i < 8192; i += 256)
            dst[i] = s[(i >> 6) * 65 + (i & 63)];
    }
}

// ---------- main kernel ----------
__global__ __launch_bounds__(128, 2)
void ptf_hmma(const float* __restrict__ p,
              const float* __restrict__ ps,
              const float* __restrict__ b0g,
              const float* __restrict__ b1g,
              const float* __restrict__ b2g,
              const float* __restrict__ W0g,
              const float* __restrict__ W3g,
              const float* __restrict__ b3g,
              float* __restrict__ out) {
    extern __shared__ uint32_t sm[];
    uint32_t* AH = sm + AH_W;                // [128][RS]
    float* bias_s = (float*)(sm + BIAS_W);   // [2][3][128]
    float* w0p_s  = (float*)(sm + W0P_W);    // [2][3][128]
    float* w3_s   = (float*)(sm + W3_W);     // [2][128]
    float* scr    = (float*)(sm + SCR_W);    // [128]

    const int tid = threadIdx.x, lane = tid & 31, wid = tid >> 5;
    const int mb = (wid & 1) * 64;        // t strip (64 rows)
    const int nb = (wid >> 1) * 64;       // h strip (64 cols)
    const int t0 = blockIdx.x * 128, b = blockIdx.y, j0 = blockIdx.z * 2;

    const uint32_t sbase = smem_u32(sm);
    const int arow_l = (lane & 7) + ((lane >> 3) & 1) * 8;
    const int akoff  = ((lane >> 4) & 1) * 16;
    const int brow_l = (lane & 7) + ((lane >> 4) & 1) * 8;
    const int bkoff  = ((lane >> 3) & 1) * 16;

    uint32_t aoffC[4];
#pragma unroll
    for (int mf = 0; mf < 4; mf++)
        aoffC[mf] = sbase + (uint32_t)((mb + mf * 16 + arow_l) * (RS * 4) + akoff);
    uint32_t boff[4];
#pragma unroll
    for (int nfp = 0; nfp < 4; nfp++)
        boff[nfp] = sbase + (uint32_t)(WB_BYTES + (nb + nfp * 16 + brow_l) * (RS * 4) + bkoff);

    // ---- stage c tile + W0(j0) via cp.async, one group ----
    {
        const uint32_t* csrc = g_c16 + ((size_t)b * 256 + blockIdx.x) * 8192;
        for (int i = tid; i < 2048; i += 128)
            cpasync16(sbase + (i >> 4) * (RS * 4) + (i & 15) * 16, csrc + i * 4);
        const uint32_t* wsrc = g_w16 + (size_t)(j0 * 3) * 8192;
        for (int i = tid; i < 2048; i += 128)
            cpasync16(sbase + WB_BYTES + (i >> 4) * (RS * 4) + (i & 15) * 16, wsrc + i * 4);
        CP_COMMIT();
    }
    // biases / W0 p-part / W3 for BOTH joints
#pragma unroll
    for (int jj = 0; jj < 2; jj++) {
        const int j = j0 + jj;
        bias_s[jj * 384 + tid]       = __ldg(b0g + j * NH + tid);
        bias_s[jj * 384 + 128 + tid] = __ldg(b1g + j * NH + tid);
        bias_s[jj * 384 + 256 + tid] = __ldg(b2g + j * NH + tid);
        const float* w0r = W0g + ((size_t)j * NH + tid) * CIN;
        w0p_s[jj * 384 + tid]       = __ldg(w0r);
        w0p_s[jj * 384 + 128 + tid] = __ldg(w0r + 1);
        w0p_s[jj * 384 + 256 + tid] = __ldg(w0r + 2);
        w3_s[jj * 128 + tid] = __ldg(W3g + j * NH + tid);
    }
    CP_WAIT0();
    __syncthreads();

    for (int jj = 0; jj < 2; jj++) {
        const int j = j0 + jj;
        float acc3[8];
#pragma unroll
        for (int s = 0; s < 8; s++) acc3[s] = 0.f;

        for (int l = 0; l < 3; l++) {
            float acc[4][8][4];
#pragma unroll
            for (int mf = 0; mf < 4; mf++)
#pragma unroll
                for (int nf = 0; nf < 8; nf++)
#pragma unroll
                    for (int q = 0; q < 4; q++) acc[mf][nf][q] = 0.f;

            const uint32_t abase = (l == 0) ? 0u : (uint32_t)AH_BYTES;
#pragma unroll
            for (int kc = 0; kc < 8; kc++) {
                uint32_t a[4][4];
#pragma unroll
                for (int mf = 0; mf < 4; mf++)
                    ldsm4(a[mf], aoffC[mf] + abase + kc * 32);
#pragma unroll
                for (int nfp = 0; nfp < 4; nfp++) {
                    uint32_t bw[4];
                    ldsm4(bw, boff[nfp] + kc * 32);
#pragma unroll
                    for (int mf = 0; mf < 4; mf++) {
                        mma16816(acc[mf][2 * nfp],     a[mf], bw[0], bw[1]);
                        mma16816(acc[mf][2 * nfp + 1], a[mf], bw[2], bw[3]);
                    }
                }
            }
            __syncthreads();   // all reads of A + W done

            if (l < 2) {
                // prefetch this joint's next-layer weights (overlaps epilogue)
                const uint32_t* src = g_w16 + (size_t)(j * 3 + l + 1) * 8192;
                for (int i = tid; i < 2048; i += 128)
                    cpasync16(sbase + WB_BYTES + (i >> 4) * (RS * 4) + (i & 15) * 16, src + i * 4);
                CP_COMMIT();

                float pva[4][3], pvb[4][3];
                if (l == 0) {
#pragma unroll
                    for (int mf = 0; mf < 4; mf++) {
                        int r0 = t0 + mb + mf * 16 + (lane >> 2);
#pragma unroll
                        for (int d = 0; d < 3; d++) {
                            const float* pp = p + ((size_t)b * NJ * 3 + j * 3 + d) * NT;
                            pva[mf][d] = __ldg(pp + r0);
                            pvb[mf][d] = __ldg(pp + r0 + 8);
                        }
                    }
                }
#pragma unroll
                for (int mf = 0; mf < 4; mf++) {
                    const int r0 = mb + mf * 16 + (lane >> 2);
#pragma unroll
                    for (int nf = 0; nf < 8; nf++) {
                        const int h = nb + nf * 8 + 2 * (lane & 3);
                        float2 bb = *(const float2*)(bias_s + jj * 384 + l * 128 + h);
                        float v0 = acc[mf][nf][0] + bb.x;
                        float v1 = acc[mf][nf][1] + bb.y;
                        float v2 = acc[mf][nf][2] + bb.x;
                        float v3 = acc[mf][nf][3] + bb.y;
                        if (l == 0) {
#pragma unroll
                            for (int d = 0; d < 3; d++) {
                                float2 w = *(const float2*)(w0p_s + jj * 384 + d * 128 + h);
                                v0 = fmaf(pva[mf][d], w.x, v0);
                                v1 = fmaf(pva[mf][d], w.y, v1);
                                v2 = fmaf(pvb[mf][d], w.x, v2);
                                v3 = fmaf(pvb[mf][d], w.y, v3);
                            }
                        }
                        v0 = fmaxf(v0, 0.f); v1 = fmaxf(v1, 0.f);
                        v2 = fmaxf(v2, 0.f); v3 = fmaxf(v3, 0.f);
                        const int wcol = h >> 1;
                        AH[r0 * RS + wcol]       = h2bits(__floats2half2_rn(v0, v1));
                        AH[(r0 + 8) * RS + wcol] = h2bits(__floats2half2_rn(v2, v3));
                    }
                }
                CP_WAIT0();
                __syncthreads();
            } else {
                // prefetch next joint's W0 (overlaps head phase)
                if (jj == 0) {
                    const uint32_t* src = g_w16 + (size_t)((j0 + 1) * 3) * 8192;
                    for (int i = tid; i < 2048; i += 128)
                        cpasync16(sbase + WB_BYTES + (i >> 4) * (RS * 4) + (i & 15) * 16, src + i * 4);
                    CP_COMMIT();
                }
                // fused head: o[t] += relu(v) . W3
#pragma unroll
                for (int mf = 0; mf < 4; mf++) {
#pragma unroll
                    for (int nf = 0; nf < 8; nf++) {
                        const int h = nb + nf * 8 + 2 * (lane & 3);
                        float2 bb = *(const float2*)(bias_s + jj * 384 + 256 + h);
                        float2 w3v = *(const float2*)(w3_s + jj * 128 + h);
                        float v0 = fmaxf(acc[mf][nf][0] + bb.x, 0.f);
                        float v1 = fmaxf(acc[mf][nf][1] + bb.y, 0.f);
                        float v2 = fmaxf(acc[mf][nf][2] + bb.x, 0.f);
                        float v3 = fmaxf(acc[mf][nf][3] + bb.y, 0.f);
                        acc3[mf * 2 + 0] += v0 * w3v.x + v1 * w3v.y;
                        acc3[mf * 2 + 1] += v2 * w3v.x + v3 * w3v.y;
                    }
                }
                scr[tid] = 0.f;
                __syncthreads();   // zero visible before atomics

                // quad shuffle reduce, then atomics into scr
#pragma unroll
                for (int s = 0; s < 8; s++) {
                    acc3[s] += __shfl_xor_sync(0xffffffffu, acc3[s], 1);
                    acc3[s] += __shfl_xor_sync(0xffffffffu, acc3[s], 2);
                }
                if ((lane & 3) == 0) {
#pragma unroll
                    for (int s = 0; s < 8; s++) {
                        int r = mb + (s >> 1) * 16 + (lane >> 2) + (s & 1) * 8;
                        atomicAdd(scr + r, acc3[s]);
                    }
                }
                __syncthreads();

                {
                    float o = scr[tid] + __ldg(b3g + j);
                    float w = __ldg(ps + ((size_t)b * NJ + j) * NT + t0 + tid);
                    atomicAdd(out + (size_t)b * NT + t0 + tid, o * w * (1.0f / 14.0f));
                }
                if (jj == 0) CP_WAIT0();
                __syncthreads();   // W0(j0+1) ready + scr reads done
            }
        }
    }
}

extern "C" void kernel_launch(void* const* d_in, const int* in_sizes, int n_in,
                              void* d_out, int out_size) {
    (void)in_sizes; (void)n_in;
    const float* p  = (const float*)d_in[0];
    // d_in[1] = z (unused by the reference)
    const float* c  = (const float*)d_in[2];
    const float* ps = (const float*)d_in[3];
    const float* W0 = (const float*)d_in[4];
    const float* b0 = (const float*)d_in[5];
    const float* W1 = (const float*)d_in[6];
    const float* b1 = (const float*)d_in[7];
    const float* W2 = (const float*)d_in[8];
    const float* b2 = (const float*)d_in[9];
    const float* W3 = (const float*)d_in[10];
    const float* b3 = (const float*)d_in[11];
    float* out = (float*)d_out;

    cudaMemsetAsync(out, 0, (size_t)out_size * sizeof(float));

    convert_all<<<554, 256>>>(W0, W1, W2, c);

    cudaFuncSetAttribute(ptf_hmma, cudaFuncAttributeMaxDynamicSharedMemorySize,
                         SMEM_BYTES);
    dim3 grid(NT / 128, NB, NJ / 2);   // 256 x 2 x 7 = 3584 CTAs
    ptf_hmma<<<grid, 128, SMEM_BYTES>>>(p, ps, b0, b1, b2, W0, W3, b3, out);
}

// round 8
// speedup vs baseline: 1.0582x; 1.0582x over previous
#include <cuda_runtime.h>
#include <cuda_fp16.h>
#include <cstdint>

#define NJ 14
#define NB 2
#define NT 32768
#define NH 128
#define CIN 131

#define RS 68                 // row stride in u32 (272 B): 16B-aligned, ldmatrix conflict-free
#define SM_WB_BYTES 34816     // W buffer after AH[128][RS]
#define BIAS_W 17408          // word offsets
#define W0P_W  17792
#define W3_W   18176
#define SCR_W  18304
#define SMEM_BYTES 74240

__device__ uint32_t g_w16[NJ * 3 * 8192];          // fp16x2 weights [j][l][h(128)][kw(64)]
__device__ uint32_t g_c16[NB * 256 * 128 * 64];    // fp16x2 c tiles [b][tile][t(128)][kw(64)]

// ---------- helpers ----------
__device__ __forceinline__ uint32_t smem_u32(const void* p) {
    uint32_t a;
    asm("{ .reg .u64 t; cvta.to.shared.u64 t, %1; cvt.u32.u64 %0, t; }" : "=r"(a) : "l"(p));
    return a;
}
__device__ __forceinline__ void ldsm4(uint32_t* r, uint32_t addr) {
    asm volatile("ldmatrix.sync.aligned.m8n8.x4.shared.b16 {%0,%1,%2,%3}, [%4];"
                 : "=r"(r[0]), "=r"(r[1]), "=r"(r[2]), "=r"(r[3]) : "r"(addr));
}
__device__ __forceinline__ void mma16816(float* d, const uint32_t* a,
                                         uint32_t b0, uint32_t b1) {
    asm volatile(
        "mma.sync.aligned.m16n8k16.row.col.f32.f16.f16.f32 "
        "{%0,%1,%2,%3}, {%4,%5,%6,%7}, {%8,%9}, {%0,%1,%2,%3};"
        : "+f"(d[0]), "+f"(d[1]), "+f"(d[2]), "+f"(d[3])
        : "r"(a[0]), "r"(a[1]), "r"(a[2]), "r"(a[3]), "r"(b0), "r"(b1));
}
__device__ __forceinline__ void cpasync16(uint32_t dst, const void* src) {
    asm volatile("cp.async.ca.shared.global [%0], [%1], 16;" :: "r"(dst), "l"(src));
}
#define CP_COMMIT() asm volatile("cp.async.commit_group;" ::: "memory")
#define CP_WAIT0()  asm volatile("cp.async.wait_group 0;" ::: "memory")

__device__ __forceinline__ uint32_t h2bits(half2 h) {
    return *reinterpret_cast<uint32_t*>(&h);
}

// ---------- fused pre-conversion: weights (blocks 0..41) + c (blocks 42..553) ----------
__global__ void convert_all(const float* __restrict__ W0,
                            const float* __restrict__ W1,
                            const float* __restrict__ W2,
                            const float* __restrict__ c) {
    __shared__ uint32_t s[128 * 65];
    int bid = blockIdx.x;
    if (bid < 42) {
        int j = bid / 3, l = bid % 3;
        const float* W = (l == 0) ? W0 : ((l == 1) ? W1 : W2);
        int K = (l == 0) ? CIN : NH;
        int koff = (l == 0) ? 3 : 0;
        uint32_t* dst = g_w16 + (size_t)(j * 3 + l) * 8192;
        for (int i = threadIdx.x; i < 8192; i += blockDim.x) {
            int h = i >> 6, kw = i & 63;
            const float* row = W + ((size_t)j * NH + h) * K + koff;
            dst[i] = h2bits(__floats2half2_rn(row[2 * kw], row[2 * kw + 1]));
        }
    } else {
        int cid = bid - 42;
        int tile = cid & 255, b = cid >> 8;
        const float* cb = c + (size_t)b * NH * NT + tile * 128;
        uint32_t* dst = g_c16 + ((size_t)b * 256 + tile) * 8192;
        for (int i = threadIdx.x; i < 8192; i += 256) {
            int t = i & 127, kw = i >> 7;
            float v0 = __ldg(cb + (size_t)(2 * kw) * NT + t);
            float v1 = __ldg(cb + (size_t)(2 * kw + 1) * NT + t);
            s[t * 65 + kw] = h2bits(__floats2half2_rn(v0, v1));
        }
        __syncthreads();
        for (int i = threadIdx.x; i < 8192; i += 256)
            dst[i] = s[(i >> 6) * 65 + (i & 63)];
    }
}

// ---------- main kernel: 256 threads, warp tile 32(M)x64(N), 2 CTAs/SM ----------
__global__ __launch_bounds__(256, 2)
void ptf_hmma(const float* __restrict__ p,
              const float* __restrict__ ps,
              const float* __restrict__ b0g,
              const float* __restrict__ b1g,
              const float* __restrict__ b2g,
              const float* __restrict__ W0g,
              const float* __restrict__ W3g,
              const float* __restrict__ b3g,
              float* __restrict__ out) {
    extern __shared__ uint32_t sm[];
    uint32_t* AH = sm;                       // [128][RS]
    float* bias_s = (float*)(sm + BIAS_W);   // [3][128]
    float* w0p_s  = (float*)(sm + W0P_W);    // [3][128]
    float* w3_s   = (float*)(sm + W3_W);     // [128]
    float* scr    = (float*)(sm + SCR_W);    // [128]

    const int tid = threadIdx.x, lane = tid & 31, wid = tid >> 5;
    const int mb = (wid & 3) * 32;        // t strip (32 rows)
    const int nb = (wid >> 2) * 64;       // h strip (64 cols)
    const int t0 = blockIdx.x * 128, b = blockIdx.y, j = blockIdx.z;

    const uint32_t sbase = smem_u32(sm);
    const int arow_l = (lane & 7) + ((lane >> 3) & 1) * 8;
    const int akoff  = ((lane >> 4) & 1) * 16;
    const int brow_l = (lane & 7) + ((lane >> 4) & 1) * 8;
    const int bkoff  = ((lane >> 3) & 1) * 16;

    uint32_t aoff[2];
#pragma unroll
    for (int mf = 0; mf < 2; mf++)
        aoff[mf] = sbase + (uint32_t)((mb + mf * 16 + arow_l) * (RS * 4) + akoff);
    uint32_t boff[4];
#pragma unroll
    for (int nfp = 0; nfp < 4; nfp++)
        boff[nfp] = sbase + (uint32_t)(SM_WB_BYTES + (nb + nfp * 16 + brow_l) * (RS * 4) + bkoff);

    // ---- stage c tile (pre-converted) + W0 via cp.async, one group ----
    {
        const uint32_t* csrc = g_c16 + ((size_t)b * 256 + blockIdx.x) * 8192;
        for (int i = tid; i < 2048; i += 256)
            cpasync16(sbase + (i >> 4) * (RS * 4) + (i & 15) * 16, csrc + i * 4);
        const uint32_t* wsrc = g_w16 + (size_t)(j * 3) * 8192;
        for (int i = tid; i < 2048; i += 256)
            cpasync16(sbase + SM_WB_BYTES + (i >> 4) * (RS * 4) + (i & 15) * 16, wsrc + i * 4);
        CP_COMMIT();
    }
    if (tid < 128) {
        bias_s[tid]       = __ldg(b0g + j * NH + tid);
        bias_s[128 + tid] = __ldg(b1g + j * NH + tid);
        bias_s[256 + tid] = __ldg(b2g + j * NH + tid);
        const float* w0r = W0g + ((size_t)j * NH + tid) * CIN;
        w0p_s[tid]       = __ldg(w0r);
        w0p_s[128 + tid] = __ldg(w0r + 1);
        w0p_s[256 + tid] = __ldg(w0r + 2);
        w3_s[tid] = __ldg(W3g + j * NH + tid);
        scr[tid] = 0.f;
    }
    CP_WAIT0();
    __syncthreads();

    float acc3[4] = {0.f, 0.f, 0.f, 0.f};

    for (int l = 0; l < 3; l++) {
        float acc[2][8][4];
#pragma unroll
        for (int mf = 0; mf < 2; mf++)
#pragma unroll
            for (int nf = 0; nf < 8; nf++)
#pragma unroll
                for (int q = 0; q < 4; q++) acc[mf][nf][q] = 0.f;

#pragma unroll
        for (int kc = 0; kc < 8; kc++) {
            uint32_t a[2][4];
#pragma unroll
            for (int mf = 0; mf < 2; mf++)
                ldsm4(a[mf], aoff[mf] + kc * 32);
#pragma unroll
            for (int nfp = 0; nfp < 4; nfp++) {
                uint32_t bw[4];
                ldsm4(bw, boff[nfp] + kc * 32);
#pragma unroll
                for (int mf = 0; mf < 2; mf++) {
                    mma16816(acc[mf][2 * nfp],     a[mf], bw[0], bw[1]);
                    mma16816(acc[mf][2 * nfp + 1], a[mf], bw[2], bw[3]);
                }
            }
        }
        __syncthreads();   // all reads of AH + W done

        if (l < 2) {
            // prefetch next layer's weights (overlaps epilogue)
            const uint32_t* src = g_w16 + (size_t)(j * 3 + l + 1) * 8192;
            for (int i = tid; i < 2048; i += 256)
                cpasync16(sbase + SM_WB_BYTES + (i >> 4) * (RS * 4) + (i & 15) * 16, src + i * 4);
            CP_COMMIT();

            float pva[2][3], pvb[2][3];
            if (l == 0) {
#pragma unroll
                for (int mf = 0; mf < 2; mf++) {
                    int r0 = t0 + mb + mf * 16 + (lane >> 2);
#pragma unroll
                    for (int d = 0; d < 3; d++) {
                        const float* pp = p + ((size_t)b * NJ * 3 + j * 3 + d) * NT;
                        pva[mf][d] = __ldg(pp + r0);
                        pvb[mf][d] = __ldg(pp + r0 + 8);
                    }
                }
            }
#pragma unroll
            for (int mf = 0; mf < 2; mf++) {
                const int r0 = mb + mf * 16 + (lane >> 2);
#pragma unroll
                for (int nf = 0; nf < 8; nf++) {
                    const int h = nb + nf * 8 + 2 * (lane & 3);
                    float2 bb = *(const float2*)(bias_s + l * 128 + h);
                    float v0 = acc[mf][nf][0] + bb.x;
                    float v1 = acc[mf][nf][1] + bb.y;
                    float v2 = acc[mf][nf][2] + bb.x;
                    float v3 = acc[mf][nf][3] + bb.y;
                    if (l == 0) {
#pragma unroll
                        for (int d = 0; d < 3; d++) {
                            float2 w = *(const float2*)(w0p_s + d * 128 + h);
                            v0 = fmaf(pva[mf][d], w.x, v0);
                            v1 = fmaf(pva[mf][d], w.y, v1);
                            v2 = fmaf(pvb[mf][d], w.x, v2);
                            v3 = fmaf(pvb[mf][d], w.y, v3);
                        }
                    }
                    v0 = fmaxf(v0, 0.f); v1 = fmaxf(v1, 0.f);
                    v2 = fmaxf(v2, 0.f); v3 = fmaxf(v3, 0.f);
                    const int wcol = h >> 1;
                    AH[r0 * RS + wcol]       = h2bits(__floats2half2_rn(v0, v1));
                    AH[(r0 + 8) * RS + wcol] = h2bits(__floats2half2_rn(v2, v3));
                }
            }
            CP_WAIT0();
        } else {
            // fused head: o[t] += relu(v) . W3
#pragma unroll
            for (int mf = 0; mf < 2; mf++) {
#pragma unroll
                for (int nf = 0; nf < 8; nf++) {
                    const int h = nb + nf * 8 + 2 * (lane & 3);
                    float2 bb = *(const float2*)(bias_s + 256 + h);
                    float2 w3v = *(const float2*)(w3_s + h);
                    float v0 = fmaxf(acc[mf][nf][0] + bb.x, 0.f);
                    float v1 = fmaxf(acc[mf][nf][1] + bb.y, 0.f);
                    float v2 = fmaxf(acc[mf][nf][2] + bb.x, 0.f);
                    float v3 = fmaxf(acc[mf][nf][3] + bb.y, 0.f);
                    acc3[mf * 2 + 0] += v0 * w3v.x + v1 * w3v.y;
                    acc3[mf * 2 + 1] += v2 * w3v.x + v3 * w3v.y;
                }
            }
        }
        __syncthreads();
    }

    // head reduce: quad shuffle, then atomics into scr (2 h-warps per t-row)
#pragma unroll
    for (int s = 0; s < 4; s++) {
        acc3[s] += __shfl_xor_sync(0xffffffffu, acc3[s], 1);
        acc3[s] += __shfl_xor_sync(0xffffffffu, acc3[s], 2);
    }
    if ((lane & 3) == 0) {
#pragma unroll
        for (int s = 0; s < 4; s++) {
            int r = mb + (s >> 1) * 16 + (lane >> 2) + (s & 1) * 8;
            atomicAdd(scr + r, acc3[s]);
        }
    }
    __syncthreads();

    if (tid < 128) {
        float o = scr[tid] + __ldg(b3g + j);
        float w = __ldg(ps + ((size_t)b * NJ + j) * NT + t0 + tid);
        atomicAdd(out + (size_t)b * NT + t0 + tid, o * w * (1.0f / 14.0f));
    }
}

extern "C" void kernel_launch(void* const* d_in, const int* in_sizes, int n_in,
                              void* d_out, int out_size) {
    (void)in_sizes; (void)n_in;
    const float* p  = (const float*)d_in[0];
    // d_in[1] = z (unused by the reference)
    const float* c  = (const float*)d_in[2];
    const float* ps = (const float*)d_in[3];
    const float* W0 = (const float*)d_in[4];
    const float* b0 = (const float*)d_in[5];
    const float* W1 = (const float*)d_in[6];
    const float* b1 = (const float*)d_in[7];
    const float* W2 = (const float*)d_in[8];
    const float* b2 = (const float*)d_in[9];
    const float* W3 = (const float*)d_in[10];
    const float* b3 = (const float*)d_in[11];
    float* out = (float*)d_out;

    cudaMemsetAsync(out, 0, (size_t)out_size * sizeof(float));

    convert_all<<<554, 256>>>(W0, W1, W2, c);

    cudaFuncSetAttribute(ptf_hmma, cudaFuncAttributeMaxDynamicSharedMemorySize,
                         SMEM_BYTES);
    dim3 grid(NT / 128, NB, NJ);   // 256 x 2 x 14 = 7168 CTAs, j slowest
    ptf_hmma<<<grid, 256, SMEM_BYTES>>>(p, ps, b0, b1, b2, W0, W3, b3, out);
}